// round 4
// baseline (speedup 1.0000x reference)
#include <cuda_runtime.h>
#include <cstdint>

#define E 256
#define SLEN 64
#define TLEN 512
#define NB 128
#define CLU 8
#define NTHR 256

// Transposed, rank-interleaved weights. WA: [k=256][1024 cols] where cols
// 128r..128r+31 = W_w rows 32r.., cols 128r+32.. = w_hh rows 96r.. .
// WX: [k=512][1024]: cols 128r..128r+95 = w_ih rows 96r.., rest zero pad.
__device__ float4 g_WA[256 * 256];
__device__ float4 g_WX[512 * 256];

__global__ void prep(const float* __restrict__ Ww, const float* __restrict__ wih,
                     const float* __restrict__ whh) {
    int idx = blockIdx.x * blockDim.x + threadIdx.x;
    float* WA = (float*)g_WA;
    float* WX = (float*)g_WX;
    if (idx < 256 * 1024) {
        int k = idx >> 10, c = idx & 1023, r = c >> 7, i = c & 127;
        WA[idx] = (i < 32) ? Ww[(32 * r + i) * 256 + k]
                           : whh[(96 * r + i - 32) * 256 + k];
    }
    int idx2 = idx - 256 * 1024;
    if (idx2 >= 0 && idx2 < 512 * 1024) {
        int k = idx2 >> 10, c = idx2 & 1023, r = c >> 7, i = c & 127;
        WX[idx2] = (i < 96) ? wih[(96 * r + i) * 512 + k] : 0.f;
    }
}

struct __align__(16) SM {
    float h_all[CLU][260];    // replicated hidden states, all 8 cluster batches
    float lninp[CLU][516];    // replicated layernormed inputs
    float v_own[E];           // own batch attention query (assembled by peers)
    float gh_own[768];
    float gx_own[768];
    float red[40];
    uint32_t msk[TLEN];       // own batch padding mask (0 = keep)
    float4 part[8 * 32 * 8];  // matvec k-partials [warp][lane][8]; also ctx scratch
};

__device__ __forceinline__ uint32_t s2u(const void* p) {
    return (uint32_t)__cvta_generic_to_shared(p);
}
__device__ __forceinline__ void stc(uint32_t a, uint32_t rk, float v) {
    uint32_t ra;
    asm volatile("mapa.shared::cluster.u32 %0,%1,%2;" : "=r"(ra) : "r"(a), "r"(rk));
    asm volatile("st.shared::cluster.f32 [%0],%1;" ::"r"(ra), "f"(v) : "memory");
}
__device__ __forceinline__ void csync() {
    asm volatile("barrier.cluster.arrive.aligned;" ::: "memory");
    asm volatile("barrier.cluster.wait.aligned;" ::: "memory");
}

// Each CTA computes its 128-column slice for all 8 batches.
// lane -> 4 consecutive cols (float4), warp -> k-partition of NT*4.
template <int NT>
__device__ __forceinline__ void matslice(const float4* __restrict__ Wm,
                                         const float* __restrict__ hb, int hstride,
                                         float4* part, int lane, int warp, int rank) {
    float acc[4][8];
#pragma unroll
    for (int q = 0; q < 4; q++)
#pragma unroll
        for (int j = 0; j < 8; j++) acc[q][j] = 0.f;
    const float4* wp = Wm + (size_t)(warp * NT * 4) * 256 + rank * 32 + lane;
    const float* hp = hb + warp * NT * 4;
#pragma unroll 2
    for (int t = 0; t < NT; t++) {
        float4 w0 = wp[0], w1 = wp[256], w2 = wp[512], w3 = wp[768];
        wp += 1024;
        float wf[16] = {w0.x, w0.y, w0.z, w0.w, w1.x, w1.y, w1.z, w1.w,
                        w2.x, w2.y, w2.z, w2.w, w3.x, w3.y, w3.z, w3.w};
#pragma unroll
        for (int bb = 0; bb < 8; bb++) {
            float4 h = *(const float4*)(hp + bb * hstride);
#pragma unroll
            for (int q = 0; q < 4; q++) {
                acc[q][bb] += wf[q] * h.x;
                acc[q][bb] += wf[4 + q] * h.y;
                acc[q][bb] += wf[8 + q] * h.z;
                acc[q][bb] += wf[12 + q] * h.w;
            }
        }
        hp += 4;
    }
    float4* pp = part + (warp * 32 + lane) * 8;
#pragma unroll
    for (int q = 0; q < 4; q++) {
        pp[q * 2] = make_float4(acc[q][0], acc[q][1], acc[q][2], acc[q][3]);
        pp[q * 2 + 1] = make_float4(acc[q][4], acc[q][5], acc[q][6], acc[q][7]);
    }
}

__device__ __forceinline__ void reduce_scatter(SM* sm, int phase, int tid, int rank) {
    int l = tid >> 3, o8 = tid & 7;
    float4 s = make_float4(0.f, 0.f, 0.f, 0.f);
#pragma unroll
    for (int w = 0; w < 8; w++) {
        float4 p = sm->part[(w * 32 + l) * 8 + o8];
        s.x += p.x; s.y += p.y; s.z += p.z; s.w += p.w;
    }
    int q = o8 >> 1, bb0 = (o8 & 1) * 4;
    int cl = 4 * l + q;
    float vals[4] = {s.x, s.y, s.z, s.w};
#pragma unroll
    for (int m = 0; m < 4; m++) {
        uint32_t bb = bb0 + m;
        if (phase == 0) {
            if (cl < 32)
                stc(s2u(&sm->v_own[32 * rank + cl]), bb, vals[m]);
            else
                stc(s2u(&sm->gh_own[96 * rank + cl - 32]), bb, vals[m]);
        } else {
            if (cl < 96) stc(s2u(&sm->gx_own[96 * rank + cl]), bb, vals[m]);
        }
    }
}

__device__ __forceinline__ float blk_sum(float v, float* red, int tid) {
#pragma unroll
    for (int o = 16; o; o >>= 1) v += __shfl_xor_sync(0xffffffffu, v, o);
    if ((tid & 31) == 0) red[tid >> 5] = v;
    __syncthreads();
    if (tid < 8) {
        v = red[tid];
#pragma unroll
        for (int o = 4; o; o >>= 1) v += __shfl_xor_sync(0xffu, v, o);
        if (tid == 0) red[32] = v;
    }
    __syncthreads();
    float r = red[32];
    __syncthreads();
    return r;
}

__global__ void __cluster_dims__(CLU, 1, 1) __launch_bounds__(NTHR, 1)
gru(const float* __restrict__ sig, const float* __restrict__ bases,
    const uint32_t* __restrict__ mask, const float* __restrict__ Wb,
    const float* __restrict__ lng, const float* __restrict__ lnb,
    const float* __restrict__ bih, const float* __restrict__ bhh,
    const float* __restrict__ h0, float* __restrict__ out) {
    extern __shared__ char smraw[];
    SM* sm = (SM*)smraw;
    int tid = threadIdx.x, lane = tid & 31, warp = tid >> 5;
    int b = blockIdx.x;
    uint32_t rank;
    asm("mov.u32 %0,%%cluster_ctarank;" : "=r"(rank));

    {
        float hv = h0[tid];
#pragma unroll
        for (int j = 0; j < CLU; j++) sm->h_all[j][tid] = hv;
        // Mask is constant across steps: hoist once. Mask arrives as a 4-byte
        // type (bool upcast to int32 0/1 or float32 0.0/1.0) — nonzero word
        // means "masked" in both encodings.
#pragma unroll
        for (int t = tid; t < TLEN; t += NTHR)
            sm->msk[t] = mask[(size_t)b * TLEN + t];
    }
    __syncthreads();
    csync();

    const float4* sig4 = (const float4*)(sig + (size_t)b * TLEN * E);

    for (int s = 0; s < SLEN; s++) {
        // ---- Phase A: v (32 rows/rank) + gh (96 rows/rank), all 8 batches
        matslice<8>(g_WA, &sm->h_all[0][0], 260, sm->part, lane, warp, rank);
        __syncthreads();
        reduce_scatter(sm, 0, tid, rank);
        csync();

        // ---- Phase B: attention for own batch (single pass, online softmax)
        sm->v_own[tid] += Wb[tid];
        __syncthreads();
        float4 vA = ((float4*)sm->v_own)[lane * 2];
        float4 vB = ((float4*)sm->v_own)[lane * 2 + 1];
        float mrun = -1e30f, Ssum = 0.f;
        float c8[8] = {0.f, 0.f, 0.f, 0.f, 0.f, 0.f, 0.f, 0.f};
        for (int j = 0; j < 64; j++) {
            int t = warp * 64 + j;
            float4 s0 = sig4[(size_t)t * 64 + lane * 2];
            float4 s1 = sig4[(size_t)t * 64 + lane * 2 + 1];
            float a = s0.x * vA.x + s0.y * vA.y + s0.z * vA.z + s0.w * vA.w +
                      s1.x * vB.x + s1.y * vB.y + s1.z * vB.z + s1.w * vB.w;
#pragma unroll
            for (int o = 16; o; o >>= 1) a += __shfl_xor_sync(0xffffffffu, a, o);
            bool msk = (sm->msk[t] != 0u);
            if (!msk && a > mrun) {
                float sc = __expf(mrun - a);
                Ssum *= sc;
#pragma unroll
                for (int i = 0; i < 8; i++) c8[i] *= sc;
                mrun = a;
            }
            float p = msk ? 0.f : __expf(a - mrun);
            Ssum += p;
            c8[0] += p * s0.x; c8[1] += p * s0.y; c8[2] += p * s0.z; c8[3] += p * s0.w;
            c8[4] += p * s1.x; c8[5] += p * s1.y; c8[6] += p * s1.z; c8[7] += p * s1.w;
        }
        float* cw = (float*)sm->part;
        ((float4*)(cw + warp * 264 + lane * 8))[0] = make_float4(c8[0], c8[1], c8[2], c8[3]);
        ((float4*)(cw + warp * 264 + lane * 8))[1] = make_float4(c8[4], c8[5], c8[6], c8[7]);
        if (lane == 0) { sm->red[16 + 2 * warp] = mrun; sm->red[17 + 2 * warp] = Ssum; }
        __syncthreads();
        float m = -1e30f;
#pragma unroll
        for (int w = 0; w < 8; w++) m = fmaxf(m, sm->red[16 + 2 * w]);
        float S = 0.f, ctx = 0.f;
#pragma unroll
        for (int w = 0; w < 8; w++) {
            float sc = __expf(sm->red[16 + 2 * w] - m);
            S += sm->red[17 + 2 * w] * sc;
            ctx += cw[w * 264 + tid] * sc;
        }
        ctx /= S;

        // ---- LayerNorm over [x, ctx] (512) + replicate lninp to cluster
        float x0 = bases[((size_t)b * SLEN + s) * E + tid];
        float s1r = blk_sum(x0 + ctx, sm->red, tid);
        float s2r = blk_sum(x0 * x0 + ctx * ctx, sm->red, tid);
        float mu = s1r * (1.f / 512.f);
        float var = s2r * (1.f / 512.f) - mu * mu;
        float rstd = rsqrtf(var + 1e-5f);
        float y0 = (x0 - mu) * rstd * lng[tid] + lnb[tid];
        float y1 = (ctx - mu) * rstd * lng[256 + tid] + lnb[256 + tid];
        uint32_t a0 = s2u(&sm->lninp[rank][tid]);
        uint32_t a1 = s2u(&sm->lninp[rank][256 + tid]);
#pragma unroll
        for (uint32_t rr = 0; rr < CLU; rr++) { stc(a0, rr, y0); stc(a1, rr, y1); }
        csync();

        // ---- Phase C: gx (96 rows/rank, K=512), all 8 batches
        matslice<16>(g_WX, &sm->lninp[0][0], 516, sm->part, lane, warp, rank);
        __syncthreads();
        reduce_scatter(sm, 1, tid, rank);
        csync();

        // ---- Phase D: GRU gates, output, broadcast h
        float gr = sm->gx_own[tid] + bih[tid] + sm->gh_own[tid] + bhh[tid];
        float gz = sm->gx_own[256 + tid] + bih[256 + tid] + sm->gh_own[256 + tid] + bhh[256 + tid];
        float hn = sm->gh_own[512 + tid] + bhh[512 + tid];
        float xn = sm->gx_own[512 + tid] + bih[512 + tid];
        float r = 1.f / (1.f + __expf(-gr));
        float z = 1.f / (1.f + __expf(-gz));
        float n = tanhf(xn + r * hn);
        float hold = sm->h_all[rank][tid];
        float hnew = (1.f - z) * n + z * hold;
        out[((size_t)b * SLEN + s) * E + tid] = hnew;
        uint32_t ah = s2u(&sm->h_all[rank][tid]);
#pragma unroll
        for (uint32_t rr = 0; rr < CLU; rr++) stc(ah, rr, hnew);
        csync();
    }
}

extern "C" void kernel_launch(void* const* d_in, const int* in_sizes, int n_in,
                              void* d_out, int out_size) {
    const float* sig = (const float*)d_in[0];
    const float* bases = (const float*)d_in[1];
    const uint32_t* mask = (const uint32_t*)d_in[2];
    const float* Ww = (const float*)d_in[3];
    const float* Wb = (const float*)d_in[4];
    const float* lng = (const float*)d_in[5];
    const float* lnb = (const float*)d_in[6];
    const float* wih = (const float*)d_in[7];
    const float* bihp = (const float*)d_in[8];
    const float* whh = (const float*)d_in[9];
    const float* bhhp = (const float*)d_in[10];
    const float* h0 = (const float*)d_in[11];
    float* out = (float*)d_out;

    cudaFuncSetAttribute(gru, cudaFuncAttributeMaxDynamicSharedMemorySize,
                         (int)sizeof(SM));
    prep<<<3072, 256>>>(Ww, wih, whh);
    gru<<<NB, NTHR, sizeof(SM)>>>(sig, bases, mask, Wb, lng, lnb, bihp, bhhp, h0, out);
}

// round 6
// speedup vs baseline: 1.2108x; 1.2108x over previous
#include <cuda_runtime.h>
#include <cstdint>

#define E 256
#define SLEN 64
#define TLEN 512
#define NB 128
#define CLU 8
#define NTHR 512

typedef unsigned long long u64;

// WA: [k=256][1024 cols]. Rank r owns cols [128r,128r+128):
//   c<32: W_w row (32r+c)  (v, scattered to batch owner)
//   c>=32: cc=c-32=3j+g: w_hh row (g*256+32r+j)  (gh triplets, kept local)
// WX: [k=512][1024]. c<96: 3j+g -> w_ih row (g*256+32r+j); c>=96: zero pad.
__device__ float4 g_WA[256 * 256];
__device__ float4 g_WX[512 * 256];

__global__ void prep(const float* __restrict__ Ww, const float* __restrict__ wih,
                     const float* __restrict__ whh) {
    int idx = blockIdx.x * blockDim.x + threadIdx.x;
    float* WA = (float*)g_WA;
    float* WX = (float*)g_WX;
    if (idx < 256 * 1024) {
        int k = idx >> 10, cg = idx & 1023, r = cg >> 7, c = cg & 127;
        if (c < 32) WA[idx] = Ww[(32 * r + c) * 256 + k];
        else {
            int cc = c - 32, j = cc / 3, g = cc - 3 * j;
            WA[idx] = whh[(g * 256 + 32 * r + j) * 256 + k];
        }
    }
    int idx2 = idx - 256 * 1024;
    if (idx2 >= 0 && idx2 < 512 * 1024) {
        int k = idx2 >> 10, cg = idx2 & 1023, r = cg >> 7, c = cg & 127;
        if (c < 96) {
            int j = c / 3, g = c - 3 * j;
            WX[idx2] = wih[(g * 256 + 32 * r + j) * 512 + k];
        } else WX[idx2] = 0.f;
    }
}

// ---------------- f32x2 helpers ---------------------------------------------
__device__ __forceinline__ u64 f2x2(float a, float b) {
    u64 r; asm("mov.b64 %0,{%1,%2};" : "=l"(r) : "f"(a), "f"(b)); return r;
}
__device__ __forceinline__ void unpk(u64 v, float& a, float& b) {
    asm("mov.b64 {%0,%1},%2;" : "=f"(a), "=f"(b) : "l"(v));
}
__device__ __forceinline__ u64 fma2(u64 a, u64 b, u64 c) {
    u64 d; asm("fma.rn.f32x2 %0,%1,%2,%3;" : "=l"(d) : "l"(a), "l"(b), "l"(c)); return d;
}
__device__ __forceinline__ u64 mul2(u64 a, u64 b) {
    u64 d; asm("mul.rn.f32x2 %0,%1,%2;" : "=l"(d) : "l"(a), "l"(b)); return d;
}
__device__ __forceinline__ u64 add2(u64 a, u64 b) {
    u64 d; asm("add.rn.f32x2 %0,%1,%2;" : "=l"(d) : "l"(a), "l"(b)); return d;
}
__device__ __forceinline__ uint32_t s2u(const void* p) {
    return (uint32_t)__cvta_generic_to_shared(p);
}
__device__ __forceinline__ void stc64(uint32_t a, uint32_t rk, u64 v) {
    uint32_t ra;
    asm volatile("mapa.shared::cluster.u32 %0,%1,%2;" : "=r"(ra) : "r"(a), "r"(rk));
    asm volatile("st.shared::cluster.u64 [%0],%1;" ::"r"(ra), "l"(v) : "memory");
}
__device__ __forceinline__ void csync() {
    asm volatile("barrier.cluster.arrive.aligned;" ::: "memory");
    asm volatile("barrier.cluster.wait.aligned;" ::: "memory");
}

struct __align__(16) SM {
    u64 hdup[256 * 8];      // (h,h) per [k][bb]
    u64 lndup[512 * 8];     // (y,y) per [k][bb]
    float part[16 * 1026];  // matvec partials; reused as attention ctx scratch
    float v_own[E];
    float ctx_s[E];
    float gh_loc[8 * 96];
    float gx_loc[8 * 96];
    uint32_t msk[TLEN];
    float2 mS[16];
    float wgtS[16];
    float sgS;
    float redA[20];
    float redB[20];
};

// 128-col slice (this rank) x 8 batches; warp = k-partition of NT*4.
template <int NT>
__device__ __forceinline__ void matslice2(const ulonglong2* __restrict__ Wq,
                                          const ulonglong2* __restrict__ hq,
                                          float* part, int lane, int warp, int rank) {
    u64 acc[2][8];
#pragma unroll
    for (int p = 0; p < 2; p++)
#pragma unroll
        for (int b = 0; b < 8; b++) acc[p][b] = 0ull;
    const ulonglong2* wp = Wq + (size_t)(warp * NT * 4) * 256 + rank * 32 + lane;
    const ulonglong2* hp = hq + (warp * NT * 4) * 4;
#pragma unroll 2
    for (int t = 0; t < NT; t++) {
        ulonglong2 w0 = wp[0], w1 = wp[256], w2 = wp[512], w3 = wp[768];
        wp += 1024;
#pragma unroll
        for (int bp = 0; bp < 4; bp++) {
            ulonglong2 h0 = hp[bp], h1 = hp[4 + bp], h2 = hp[8 + bp], h3 = hp[12 + bp];
            int b0 = 2 * bp, b1 = 2 * bp + 1;
            acc[0][b0] = fma2(w0.x, h0.x, acc[0][b0]); acc[1][b0] = fma2(w0.y, h0.x, acc[1][b0]);
            acc[0][b1] = fma2(w0.x, h0.y, acc[0][b1]); acc[1][b1] = fma2(w0.y, h0.y, acc[1][b1]);
            acc[0][b0] = fma2(w1.x, h1.x, acc[0][b0]); acc[1][b0] = fma2(w1.y, h1.x, acc[1][b0]);
            acc[0][b1] = fma2(w1.x, h1.y, acc[0][b1]); acc[1][b1] = fma2(w1.y, h1.y, acc[1][b1]);
            acc[0][b0] = fma2(w2.x, h2.x, acc[0][b0]); acc[1][b0] = fma2(w2.y, h2.x, acc[1][b0]);
            acc[0][b1] = fma2(w2.x, h2.y, acc[0][b1]); acc[1][b1] = fma2(w2.y, h2.y, acc[1][b1]);
            acc[0][b0] = fma2(w3.x, h3.x, acc[0][b0]); acc[1][b0] = fma2(w3.y, h3.x, acc[1][b0]);
            acc[0][b1] = fma2(w3.x, h3.y, acc[0][b1]); acc[1][b1] = fma2(w3.y, h3.y, acc[1][b1]);
        }
        hp += 16;
    }
#pragma unroll
    for (int p = 0; p < 2; p++)
#pragma unroll
        for (int b = 0; b < 8; b++) {
            int x = b * 128 + 4 * lane + 2 * p;
            *(u64*)(part + warp * 1026 + x) = acc[p][b];
        }
}

__device__ __forceinline__ void mat_reduce(SM* sm, int tid, int rank, int phase) {
    int x = 2 * tid;
    u64 s = 0ull;
#pragma unroll
    for (int w = 0; w < 16; w++) s = add2(s, *(const u64*)(sm->part + w * 1026 + x));
    int bb = x >> 7, c = x & 127;
    if (phase == 0) {
        if (c < 32) stc64(s2u(&sm->v_own[32 * rank + c]), (uint32_t)bb, s);
        else *(u64*)(&sm->gh_loc[bb * 96 + (c - 32)]) = s;
    } else {
        if (c < 96) *(u64*)(&sm->gx_loc[bb * 96 + c]) = s;
    }
}

__device__ __forceinline__ float dotp(ulonglong2 ra, ulonglong2 rb,
                                      ulonglong2 va, ulonglong2 vb) {
    u64 a = mul2(ra.x, va.x);
    a = fma2(ra.y, va.y, a);
    a = fma2(rb.x, vb.x, a);
    a = fma2(rb.y, vb.y, a);
    float lo, hi; unpk(a, lo, hi);
    return lo + hi;
}

__global__ void __cluster_dims__(CLU, 1, 1) __launch_bounds__(NTHR, 1)
gru(const float* __restrict__ sig, const float* __restrict__ bases,
    const uint32_t* __restrict__ mask, const float* __restrict__ Wb,
    const float* __restrict__ lng, const float* __restrict__ lnb,
    const float* __restrict__ bih, const float* __restrict__ bhh,
    const float* __restrict__ h0, float* __restrict__ out) {
    extern __shared__ char smraw[];
    SM* sm = (SM*)smraw;
    const int tid = threadIdx.x, lane = tid & 31, warp = tid >> 5;
    const int b = blockIdx.x;
    uint32_t rank;
    asm("mov.u32 %0,%%cluster_ctarank;" : "=r"(rank));
    const float NEGINF = __int_as_float(0xff800000);

    // per-thread constants
    float wbr = 0.f, bihr = 0.f, bihz = 0.f, bihn = 0.f;
    float bhhr = 0.f, bhhz = 0.f, bhhn = 0.f, hreg = 0.f;
    const int gj = tid & 31, gbb = tid >> 5;  // gate mapping for tid<256
    if (tid < 256) {
        wbr = Wb[tid];
        int i = 32 * rank + gj;
        bihr = bih[i]; bihz = bih[256 + i]; bihn = bih[512 + i];
        bhhr = bhh[i]; bhhz = bhh[256 + i]; bhhn = bhh[512 + i];
        hreg = h0[i];
        u64 hv = f2x2(h0[tid], h0[tid]);
#pragma unroll
        for (int bb = 0; bb < 8; bb++) sm->hdup[tid * 8 + bb] = hv;
    }
    const float lngr = lng[tid], lnbr = lnb[tid];
    for (int t = tid; t < TLEN; t += NTHR) sm->msk[t] = mask[(size_t)b * TLEN + t];
    __syncthreads();
    csync();

    const ulonglong2* sq = (const ulonglong2*)(sig + (size_t)b * TLEN * E);
    const int b_base = b & ~7;

    for (int s = 0; s < SLEN; s++) {
        // ===== Phase A: v (scatter to owner) + gh (local), all 8 batches ====
        matslice2<4>((const ulonglong2*)g_WA, (const ulonglong2*)sm->hdup,
                     sm->part, lane, warp, rank);
        __syncthreads();
        mat_reduce(sm, tid, rank, 0);
        csync();

        // ===== Attention (own batch), 32 t per warp, groups of 4 ============
        if (tid < 256) sm->v_own[tid] += wbr;
        __syncthreads();
        ulonglong2 va = ((const ulonglong2*)sm->v_own)[2 * lane];
        ulonglong2 vb = ((const ulonglong2*)sm->v_own)[2 * lane + 1];
        float mrun = -1e30f, Ss = 0.f;
        u64 c0 = 0, c1 = 0, c2 = 0, c3 = 0;
#pragma unroll 2
        for (int g = 0; g < 8; g++) {
            int t0 = warp * 32 + g * 4;
            ulonglong2 r0a = sq[(size_t)(t0 + 0) * 64 + 2 * lane];
            ulonglong2 r0b = sq[(size_t)(t0 + 0) * 64 + 2 * lane + 1];
            ulonglong2 r1a = sq[(size_t)(t0 + 1) * 64 + 2 * lane];
            ulonglong2 r1b = sq[(size_t)(t0 + 1) * 64 + 2 * lane + 1];
            ulonglong2 r2a = sq[(size_t)(t0 + 2) * 64 + 2 * lane];
            ulonglong2 r2b = sq[(size_t)(t0 + 2) * 64 + 2 * lane + 1];
            ulonglong2 r3a = sq[(size_t)(t0 + 3) * 64 + 2 * lane];
            ulonglong2 r3b = sq[(size_t)(t0 + 3) * 64 + 2 * lane + 1];
            float a0 = dotp(r0a, r0b, va, vb), a1 = dotp(r1a, r1b, va, vb);
            float a2 = dotp(r2a, r2b, va, vb), a3 = dotp(r3a, r3b, va, vb);
#pragma unroll
            for (int o = 16; o; o >>= 1) {
                a0 += __shfl_xor_sync(0xffffffffu, a0, o);
                a1 += __shfl_xor_sync(0xffffffffu, a1, o);
                a2 += __shfl_xor_sync(0xffffffffu, a2, o);
                a3 += __shfl_xor_sync(0xffffffffu, a3, o);
            }
            if (sm->msk[t0 + 0]) a0 = NEGINF;
            if (sm->msk[t0 + 1]) a1 = NEGINF;
            if (sm->msk[t0 + 2]) a2 = NEGINF;
            if (sm->msk[t0 + 3]) a3 = NEGINF;
            float mg = fmaxf(fmaxf(a0, a1), fmaxf(a2, a3));
            if (mg > mrun) {
                float sc = __expf(mrun - mg);
                mrun = mg; Ss *= sc;
                u64 sc2 = f2x2(sc, sc);
                c0 = mul2(c0, sc2); c1 = mul2(c1, sc2);
                c2 = mul2(c2, sc2); c3 = mul2(c3, sc2);
            }
            float p0 = __expf(a0 - mrun), p1 = __expf(a1 - mrun);
            float p2 = __expf(a2 - mrun), p3 = __expf(a3 - mrun);
            Ss += (p0 + p1) + (p2 + p3);
            u64 q0 = f2x2(p0, p0), q1 = f2x2(p1, p1), q2 = f2x2(p2, p2), q3 = f2x2(p3, p3);
            c0 = fma2(q0, r0a.x, c0); c1 = fma2(q0, r0a.y, c1);
            c2 = fma2(q0, r0b.x, c2); c3 = fma2(q0, r0b.y, c3);
            c0 = fma2(q1, r1a.x, c0); c1 = fma2(q1, r1a.y, c1);
            c2 = fma2(q1, r1b.x, c2); c3 = fma2(q1, r1b.y, c3);
            c0 = fma2(q2, r2a.x, c0); c1 = fma2(q2, r2a.y, c1);
            c2 = fma2(q2, r2b.x, c2); c3 = fma2(q2, r2b.y, c3);
            c0 = fma2(q3, r3a.x, c0); c1 = fma2(q3, r3a.y, c1);
            c2 = fma2(q3, r3b.x, c2); c3 = fma2(q3, r3b.y, c3);
        }
        {
            u64* cw = (u64*)sm->part + warp * 132 + lane * 4;
            cw[0] = c0; cw[1] = c1; cw[2] = c2; cw[3] = c3;
            if (lane == 0) sm->mS[warp] = make_float2(mrun, Ss);
        }
        __syncthreads();
        if (tid < 32) {
            float mw = (lane < 16) ? sm->mS[lane].x : NEGINF;
            float Sw = (lane < 16) ? sm->mS[lane].y : 0.f;
            float m = mw;
#pragma unroll
            for (int o = 16; o; o >>= 1) m = fmaxf(m, __shfl_xor_sync(0xffffffffu, m, o));
            float wgt = __expf(mw - m);
            float Sc = Sw * wgt;
#pragma unroll
            for (int o = 16; o; o >>= 1) Sc += __shfl_xor_sync(0xffffffffu, Sc, o);
            if (lane < 16) sm->wgtS[lane] = wgt;
            if (lane == 0) sm->sgS = Sc;
        }
        __syncthreads();
        if (tid < 256) {
            float acc = 0.f;
#pragma unroll
            for (int w = 0; w < 16; w++) acc += sm->part[w * 264 + tid] * sm->wgtS[w];
            sm->ctx_s[tid] = acc / sm->sgS;
        }
        __syncthreads();

        // ===== LayerNorm over [x, ctx] and broadcast (y,y) to cluster =======
        float xv = (tid < 256) ? bases[((size_t)b * SLEN + s) * E + tid]
                               : sm->ctx_s[tid - 256];
        {
            float s1 = xv, s2 = xv * xv;
#pragma unroll
            for (int o = 16; o; o >>= 1) {
                s1 += __shfl_xor_sync(0xffffffffu, s1, o);
                s2 += __shfl_xor_sync(0xffffffffu, s2, o);
            }
            if (lane == 0) { sm->redA[warp] = s1; sm->redB[warp] = s2; }
            __syncthreads();
            if (tid < 32) {
                float x1 = (lane < 16) ? sm->redA[lane] : 0.f;
                float x2 = (lane < 16) ? sm->redB[lane] : 0.f;
#pragma unroll
                for (int o = 16; o; o >>= 1) {
                    x1 += __shfl_xor_sync(0xffffffffu, x1, o);
                    x2 += __shfl_xor_sync(0xffffffffu, x2, o);
                }
                if (lane == 0) { sm->redA[16] = x1; sm->redB[16] = x2; }
            }
            __syncthreads();
            float mu = sm->redA[16] * (1.f / 512.f);
            float var = sm->redB[16] * (1.f / 512.f) - mu * mu;
            float rstd = rsqrtf(var + 1e-5f);
            float y = (xv - mu) * rstd * lngr + lnbr;
            u64 y2 = f2x2(y, y);
            uint32_t addr = s2u(&sm->lndup[tid * 8 + rank]);
#pragma unroll
            for (uint32_t rr = 0; rr < CLU; rr++) stc64(addr, rr, y2);
        }
        csync();

        // ===== Phase C: gx (local triplets), all 8 batches ==================
        matslice2<8>((const ulonglong2*)g_WX, (const ulonglong2*)sm->lndup,
                     sm->part, lane, warp, rank);
        __syncthreads();
        mat_reduce(sm, tid, rank, 1);
        __syncthreads();

        // ===== Gates for this rank's 32 h-indices, all 8 batches ============
        if (tid < 256) {
            int base = gbb * 96 + 3 * gj;
            float gxr = sm->gx_loc[base], gxz = sm->gx_loc[base + 1], gxn = sm->gx_loc[base + 2];
            float ghr = sm->gh_loc[base], ghz = sm->gh_loc[base + 1], ghn = sm->gh_loc[base + 2];
            float r = 1.f / (1.f + __expf(-(gxr + bihr + ghr + bhhr)));
            float z = 1.f / (1.f + __expf(-(gxz + bihz + ghz + bhhz)));
            float n = tanhf(gxn + bihn + r * (ghn + bhhn));
            hreg = (1.f - z) * n + z * hreg;
            int i = 32 * rank + gj;
            out[(((size_t)(b_base + gbb)) * SLEN + s) * E + i] = hreg;
            u64 h2 = f2x2(hreg, hreg);
            uint32_t ah = s2u(&sm->hdup[i * 8 + gbb]);
#pragma unroll
            for (uint32_t rr = 0; rr < CLU; rr++) stc64(ah, rr, h2);
        }
        csync();
    }
}

extern "C" void kernel_launch(void* const* d_in, const int* in_sizes, int n_in,
                              void* d_out, int out_size) {
    const float* sig = (const float*)d_in[0];
    const float* bases = (const float*)d_in[1];
    const uint32_t* mask = (const uint32_t*)d_in[2];
    const float* Ww = (const float*)d_in[3];
    const float* Wb = (const float*)d_in[4];
    const float* lng = (const float*)d_in[5];
    const float* lnb = (const float*)d_in[6];
    const float* wih = (const float*)d_in[7];
    const float* bihp = (const float*)d_in[8];
    const float* whh = (const float*)d_in[9];
    const float* bhhp = (const float*)d_in[10];
    const float* h0 = (const float*)d_in[11];
    float* out = (float*)d_out;

    cudaFuncSetAttribute(gru, cudaFuncAttributeMaxDynamicSharedMemorySize,
                         (int)sizeof(SM));
    prep<<<3072, 256>>>(Ww, wih, whh);
    gru<<<NB, NTHR, sizeof(SM)>>>(sig, bases, mask, Wb, lng, lnb, bihp, bhhp, h0, out);
}